// round 3
// baseline (speedup 1.0000x reference)
#include <cuda_runtime.h>
#include <cuda_bf16.h>

#define Bb 256
#define Tt 1024
#define INF 128
#define Hh 10
#define OUTD 128
#define BT (Bb*Tt)

// Scratch (no cudaMalloc allowed): device globals
__device__ float g_xp0[(size_t)BT * Hh];   // [BT][10]
__device__ float g_out2[(size_t)BT * Hh];  // [BT][10]

// ---------------------------------------------------------------------------
// Kernel 1: xp0[row][h] = dot(x[row,:], W_ih0[h,:]) + b_ih0[h] + b_hh0[h]
// Tile-staged: block loads 256 rows x 128 cols of x with fully COALESCED
// scalar LDG into smem (stride 129 -> bank (r+c)%32, conflict-free store AND
// per-row load), then thread-per-row compute out of smem.
// ---------------------------------------------------------------------------
__global__ __launch_bounds__(256) void k1_inproj(
    const float* __restrict__ x,
    const float* __restrict__ W_ih0,
    const float* __restrict__ b_ih0,
    const float* __restrict__ b_hh0)
{
    extern __shared__ float xs[];            // [256][129]
    __shared__ float4 Wq[128][3];            // Wq[f][g] = W_ih0[4g..4g+3][f]
    __shared__ float bs[16];
    int tid = threadIdx.x;
    for (int i = tid; i < 128 * 3; i += 256) {
        int f = i / 3, g = i % 3;
        float4 v;
        v.x = (4*g+0 < Hh) ? W_ih0[(4*g+0)*128 + f] : 0.f;
        v.y = (4*g+1 < Hh) ? W_ih0[(4*g+1)*128 + f] : 0.f;
        v.z = (4*g+2 < Hh) ? W_ih0[(4*g+2)*128 + f] : 0.f;
        v.w = (4*g+3 < Hh) ? W_ih0[(4*g+3)*128 + f] : 0.f;
        Wq[f][g] = v;
    }
    if (tid < Hh) bs[tid] = b_ih0[tid] + b_hh0[tid];

    // Stage tile: coalesced scalar loads (consecutive lanes -> consecutive addr)
    const float* xrow = x + (size_t)blockIdx.x * 256 * 128;
    #pragma unroll 8
    for (int i = tid; i < 256 * 128; i += 256) {
        int r = i >> 7, c = i & 127;
        xs[r * 129 + c] = xrow[i];
    }
    __syncthreads();

    // Compute: thread tid owns row tid of the tile.
    float acc[Hh];
    #pragma unroll
    for (int h = 0; h < Hh; h++) acc[h] = bs[h];

    const float* xr = xs + tid * 129;
    #pragma unroll 16
    for (int f = 0; f < 128; f++) {
        float xv = xr[f];
        float4 wa = Wq[f][0], wb = Wq[f][1], wc = Wq[f][2];
        acc[0] = fmaf(xv, wa.x, acc[0]);
        acc[1] = fmaf(xv, wa.y, acc[1]);
        acc[2] = fmaf(xv, wa.z, acc[2]);
        acc[3] = fmaf(xv, wa.w, acc[3]);
        acc[4] = fmaf(xv, wb.x, acc[4]);
        acc[5] = fmaf(xv, wb.y, acc[5]);
        acc[6] = fmaf(xv, wb.z, acc[6]);
        acc[7] = fmaf(xv, wb.w, acc[7]);
        acc[8] = fmaf(xv, wc.x, acc[8]);
        acc[9] = fmaf(xv, wc.y, acc[9]);
    }
    float* o = g_xp0 + ((size_t)blockIdx.x * 256 + tid) * Hh;
    #pragma unroll
    for (int h = 0; h < Hh; h++) o[h] = acc[h];
}

// ---------------------------------------------------------------------------
// Kernel 2: fused 2-layer ReLU RNN scan. ONE WARP handles TWO batches
// (independent chains interleaved -> stalls of one absorb issue of the other).
// Lane j owns element j of h0/h1 for both batches; weights lane-indexed
// (shared across the two batches). 20 shfl per batch-step.
// ---------------------------------------------------------------------------
__global__ __launch_bounds__(32) void k2_scan(
    const float* __restrict__ W_hh0,
    const float* __restrict__ W_ih1,
    const float* __restrict__ W_hh1,
    const float* __restrict__ b_ih1,
    const float* __restrict__ b_hh1,
    float* __restrict__ dout)
{
    const unsigned FULL = 0xffffffffu;
    int warp = blockIdx.x;                 // 128 warps, 2 batches each
    int lane = threadIdx.x & 31;
    int j = lane < Hh ? lane : Hh - 1;
    int bA = warp * 2, bB = warp * 2 + 1;

    float w0r[Hh], wi1r[Hh], w1r[Hh];
    #pragma unroll
    for (int k = 0; k < Hh; k++) {
        w0r[k]  = W_hh0[j * Hh + k];
        wi1r[k] = W_ih1[j * Hh + k];
        w1r[k]  = W_hh1[j * Hh + k];
    }
    float bias1 = b_ih1[j] + b_hh1[j];

    const float* xpA = g_xp0 + (size_t)bA * Tt * Hh;
    const float* xpB = g_xp0 + (size_t)bB * Tt * Hh;
    float* oA = g_out2 + (size_t)bA * Tt * Hh;
    float* oB = g_out2 + (size_t)bB * Tt * Hh;

    float v0A[Hh], v1A[Hh], v0B[Hh], v1B[Hh];
    #pragma unroll
    for (int k = 0; k < Hh; k++) { v0A[k]=0.f; v1A[k]=0.f; v0B[k]=0.f; v1B[k]=0.f; }
    float lA0 = 0.f, lA1 = 0.f, lB0 = 0.f, lB1 = 0.f;

    float xaA[4], xbA[4], xaB[4], xbB[4];
    #pragma unroll
    for (int d = 0; d < 4; d++) { xaA[d] = xpA[d*Hh + j]; xaB[d] = xpB[d*Hh + j]; }

    for (int tb = 0; tb < Tt; tb += 4) {
        if (tb + 4 < Tt) {
            #pragma unroll
            for (int d = 0; d < 4; d++) {
                xbA[d] = xpA[(tb+4+d)*Hh + j];
                xbB[d] = xpB[(tb+4+d)*Hh + j];
            }
        }
        #pragma unroll
        for (int d = 0; d < 4; d++) {
            // layer-1 recurrent dots (off critical path), both batches
            float rA0 = bias1, rA1 = 0.f, rB0 = bias1, rB1 = 0.f;
            #pragma unroll
            for (int k = 0; k < Hh; k += 2) {
                rA0 = fmaf(w1r[k],   v1A[k],   rA0);
                rB0 = fmaf(w1r[k],   v1B[k],   rB0);
                rA1 = fmaf(w1r[k+1], v1A[k+1], rA1);
                rB1 = fmaf(w1r[k+1], v1B[k+1], rB1);
            }
            // layer-0 updates, interleaved
            float aA0 = xaA[d], aA1 = 0.f, aB0 = xaB[d], aB1 = 0.f;
            #pragma unroll
            for (int k = 0; k < Hh; k += 2) {
                aA0 = fmaf(w0r[k],   v0A[k],   aA0);
                aB0 = fmaf(w0r[k],   v0B[k],   aB0);
                aA1 = fmaf(w0r[k+1], v0A[k+1], aA1);
                aB1 = fmaf(w0r[k+1], v0B[k+1], aB1);
            }
            float h0A = fmaxf(aA0 + aA1, 0.f);
            float h0B = fmaxf(aB0 + aB1, 0.f);

            // rebroadcast h0 (both batches interleaved: 20 shfls, independent)
            #pragma unroll
            for (int k = 0; k < Hh; k++) {
                v0A[k] = __shfl_sync(FULL, h0A, k);
                v0B[k] = __shfl_sync(FULL, h0B, k);
            }

            // layer-1 input dots
            float cA0 = rA0, cA1 = rA1, cB0 = rB0, cB1 = rB1;
            #pragma unroll
            for (int k = 0; k < Hh; k += 2) {
                cA0 = fmaf(wi1r[k],   v0A[k],   cA0);
                cB0 = fmaf(wi1r[k],   v0B[k],   cB0);
                cA1 = fmaf(wi1r[k+1], v0A[k+1], cA1);
                cB1 = fmaf(wi1r[k+1], v0B[k+1], cB1);
            }
            float h1A = fmaxf(cA0 + cA1, 0.f);
            float h1B = fmaxf(cB0 + cB1, 0.f);

            float* sA = oA + (size_t)(tb + d) * Hh + lane;
            float* sB = oB + (size_t)(tb + d) * Hh + lane;
            if (lane < Hh) *sA = h1A;
            if (lane < Hh) *sB = h1B;

            #pragma unroll
            for (int k = 0; k < Hh; k++) {
                v1A[k] = __shfl_sync(FULL, h1A, k);
                v1B[k] = __shfl_sync(FULL, h1B, k);
            }
            lA0 = h0A; lA1 = h1A; lB0 = h0B; lB1 = h1B;
        }
        #pragma unroll
        for (int d = 0; d < 4; d++) { xaA[d] = xbA[d]; xaB[d] = xbB[d]; }
    }

    float* hid = dout + (size_t)BT * OUTD;       // hidden: [2][B][H]
    if (lane < Hh) {
        hid[bA * Hh + lane] = lA0;
        hid[bB * Hh + lane] = lB0;
        hid[Bb * Hh + bA * Hh + lane] = lA1;
        hid[Bb * Hh + bB * Hh + lane] = lB1;
    }
}

// ---------------------------------------------------------------------------
// Kernel 3: logits = out2 @ W_lin^T + b_lin, softmax over 128.
// One warp per row; lane handles outputs 4l..4l+3; coalesced STG.128.
// ---------------------------------------------------------------------------
__global__ __launch_bounds__(256) void k3_head(
    const float* __restrict__ W_lin,
    const float* __restrict__ b_lin,
    float* __restrict__ out)
{
    const unsigned FULL = 0xffffffffu;
    __shared__ float Wl[OUTD * Hh];
    __shared__ float bl[OUTD];
    int tid = threadIdx.x;
    for (int i = tid; i < OUTD * Hh; i += blockDim.x) Wl[i] = W_lin[i];
    for (int i = tid; i < OUTD; i += blockDim.x) bl[i] = b_lin[i];
    __syncthreads();

    int lane = tid & 31;
    int wib  = tid >> 5;
    float wl[4][Hh], bb[4];
    #pragma unroll
    for (int c = 0; c < 4; c++) {
        int o = 4 * lane + c;
        bb[c] = bl[o];
        #pragma unroll
        for (int k = 0; k < Hh; k++) wl[c][k] = Wl[o * Hh + k];
    }

    int wpb = blockDim.x >> 5;
    int gw  = blockIdx.x * wpb + wib;
    int nw  = gridDim.x * wpb;
    for (int row = gw; row < BT; row += nw) {
        float v = g_out2[(size_t)row * Hh + (lane < Hh ? lane : 0)];
        float hk[Hh];
        #pragma unroll
        for (int k = 0; k < Hh; k++) hk[k] = __shfl_sync(FULL, v, k);

        float acc[4];
        #pragma unroll
        for (int c = 0; c < 4; c++) {
            acc[c] = bb[c];
            #pragma unroll
            for (int k = 0; k < Hh; k++) acc[c] = fmaf(hk[k], wl[c][k], acc[c]);
        }
        float m = fmaxf(fmaxf(acc[0], acc[1]), fmaxf(acc[2], acc[3]));
        #pragma unroll
        for (int s = 16; s > 0; s >>= 1)
            m = fmaxf(m, __shfl_xor_sync(FULL, m, s));
        float e0 = __expf(acc[0] - m), e1 = __expf(acc[1] - m);
        float e2 = __expf(acc[2] - m), e3 = __expf(acc[3] - m);
        float s = e0 + e1 + e2 + e3;
        #pragma unroll
        for (int sh = 16; sh > 0; sh >>= 1)
            s += __shfl_xor_sync(FULL, s, sh);
        float r = __frcp_rn(s);
        float4 res = make_float4(e0 * r, e1 * r, e2 * r, e3 * r);
        ((float4*)(out + (size_t)row * OUTD))[lane] = res;
    }
}

// ---------------------------------------------------------------------------
extern "C" void kernel_launch(void* const* d_in, const int* in_sizes, int n_in,
                              void* d_out, int out_size)
{
    const float* x      = (const float*)d_in[0];
    const float* W_ih0  = (const float*)d_in[1];
    const float* W_hh0  = (const float*)d_in[2];
    const float* b_ih0  = (const float*)d_in[3];
    const float* b_hh0  = (const float*)d_in[4];
    const float* W_ih1  = (const float*)d_in[5];
    const float* W_hh1  = (const float*)d_in[6];
    const float* b_ih1  = (const float*)d_in[7];
    const float* b_hh1  = (const float*)d_in[8];
    const float* W_lin  = (const float*)d_in[9];
    const float* b_lin  = (const float*)d_in[10];
    float* out = (float*)d_out;

    static bool attr_set = false;
    if (!attr_set) {
        cudaFuncSetAttribute(k1_inproj, cudaFuncAttributeMaxDynamicSharedMemorySize,
                             256 * 129 * 4);
        attr_set = true;
    }

    k1_inproj<<<1024, 256, 256 * 129 * 4>>>(x, W_ih0, b_ih0, b_hh0);
    k2_scan<<<128, 32>>>(W_hh0, W_ih1, W_hh1, b_ih1, b_hh1, out); // 2 batches/warp
    k3_head<<<2048, 256>>>(W_lin, b_lin, out);                    // grid-stride rows
}

// round 4
// speedup vs baseline: 1.4351x; 1.4351x over previous
#include <cuda_runtime.h>
#include <cuda_bf16.h>

#define Bb 256
#define Tt 1024
#define INF 128
#define Hh 10
#define OUTD 128
#define BT (Bb*Tt)

// Scratch (no cudaMalloc allowed): device globals
__device__ float g_xp0[(size_t)BT * Hh];   // [BT][10]
__device__ float g_out2[(size_t)BT * Hh];  // [BT][10]

// ---------------------------------------------------------------------------
// Kernel 1: xp0[row][h] = dot(x[row,:], W_ih0[h,:]) + b_ih0[h] + b_hh0[h]
// 128-row tile staged coalesced into 66KB smem (3 blocks/SM co-resident so
// stage and compute phases of different blocks overlap). Pad 129 ->
// conflict-free on both the coalesced store and the per-row read.
// ---------------------------------------------------------------------------
__global__ __launch_bounds__(128) void k1_inproj(
    const float* __restrict__ x,
    const float* __restrict__ W_ih0,
    const float* __restrict__ b_ih0,
    const float* __restrict__ b_hh0)
{
    __shared__ float xs[128 * 129];
    __shared__ float4 Wq[128][3];            // Wq[f][g] = W_ih0[4g..4g+3][f]
    __shared__ float bs[16];
    int tid = threadIdx.x;
    for (int i = tid; i < 128 * 3; i += 128) {
        int f = i / 3, g = i % 3;
        float4 v;
        v.x = (4*g+0 < Hh) ? W_ih0[(4*g+0)*128 + f] : 0.f;
        v.y = (4*g+1 < Hh) ? W_ih0[(4*g+1)*128 + f] : 0.f;
        v.z = (4*g+2 < Hh) ? W_ih0[(4*g+2)*128 + f] : 0.f;
        v.w = (4*g+3 < Hh) ? W_ih0[(4*g+3)*128 + f] : 0.f;
        Wq[f][g] = v;
    }
    if (tid < Hh) bs[tid] = b_ih0[tid] + b_hh0[tid];

    // Stage tile: fully coalesced scalar loads.
    const float* xrow = x + (size_t)blockIdx.x * 128 * 128;
    #pragma unroll 16
    for (int i = tid; i < 128 * 128; i += 128) {
        xs[(i >> 7) * 129 + (i & 127)] = xrow[i];
    }
    __syncthreads();

    // Compute: thread tid owns row tid of the tile.
    float acc[Hh];
    #pragma unroll
    for (int h = 0; h < Hh; h++) acc[h] = bs[h];

    const float* xr = xs + tid * 129;
    #pragma unroll 8
    for (int f = 0; f < 128; f++) {
        float xv = xr[f];
        float4 wa = Wq[f][0], wb = Wq[f][1], wc = Wq[f][2];
        acc[0] = fmaf(xv, wa.x, acc[0]);
        acc[1] = fmaf(xv, wa.y, acc[1]);
        acc[2] = fmaf(xv, wa.z, acc[2]);
        acc[3] = fmaf(xv, wa.w, acc[3]);
        acc[4] = fmaf(xv, wb.x, acc[4]);
        acc[5] = fmaf(xv, wb.y, acc[5]);
        acc[6] = fmaf(xv, wb.z, acc[6]);
        acc[7] = fmaf(xv, wb.w, acc[7]);
        acc[8] = fmaf(xv, wc.x, acc[8]);
        acc[9] = fmaf(xv, wc.y, acc[9]);
    }
    float* o = g_xp0 + ((size_t)blockIdx.x * 128 + tid) * Hh;
    #pragma unroll
    for (int h = 0; h < Hh; h++) o[h] = acc[h];
}

// ---------------------------------------------------------------------------
// Kernel 2: fused 2-layer ReLU RNN, layer-1 pipelined ONE STEP BEHIND layer-0.
// At iter t: compute h0[t] (from v0=h0[t-1]) and h1[t-1] (from v0=h0[t-1],
// v1=h1[t-2]) -> both depend only on the PREVIOUS broadcast, so the step has
// a single shfl-latency stage and all 20 shfls are independent.
// One warp per batch, 256 warps in 64 blocks.
// ---------------------------------------------------------------------------
__global__ __launch_bounds__(128) void k2_scan(
    const float* __restrict__ W_hh0,
    const float* __restrict__ W_ih1,
    const float* __restrict__ W_hh1,
    const float* __restrict__ b_ih1,
    const float* __restrict__ b_hh1,
    float* __restrict__ dout)
{
    const unsigned FULL = 0xffffffffu;
    int warp = blockIdx.x * 4 + (threadIdx.x >> 5);   // = batch b
    int lane = threadIdx.x & 31;
    int j = lane < Hh ? lane : Hh - 1;

    float w0r[Hh], wi1r[Hh], w1r[Hh];
    #pragma unroll
    for (int k = 0; k < Hh; k++) {
        w0r[k]  = W_hh0[j * Hh + k];
        wi1r[k] = W_ih1[j * Hh + k];
        w1r[k]  = W_hh1[j * Hh + k];
    }
    float bias1 = b_ih1[j] + b_hh1[j];

    const float* xp = g_xp0 + (size_t)warp * Tt * Hh;
    float* o2 = g_out2 + (size_t)warp * Tt * Hh;

    float v0[Hh], v1[Hh];
    #pragma unroll
    for (int k = 0; k < Hh; k++) { v0[k] = 0.f; v1[k] = 0.f; }

    float xa[4], xb[4];
    #pragma unroll
    for (int d = 0; d < 4; d++) xa[d] = xp[d * Hh + j];

    // ---- t = 0 peeled: h0[0] = relu(xp[0]) (v0 = 0), no h1 yet ----
    float h0n = fmaxf(xa[0], 0.f);
    float h1n = 0.f;
    #pragma unroll
    for (int k = 0; k < Hh; k++) v0[k] = __shfl_sync(FULL, h0n, k);

    // macro-free step body as a lambda
    auto step = [&](float xv, int t) {
        // h1[t-1]: wi1.v0 + w1.v1 (4 accumulator chains)
        float r0 = bias1, r1 = 0.f, r2 = 0.f, r3 = 0.f;
        #pragma unroll
        for (int k = 0; k < Hh; k += 2) {
            r0 = fmaf(wi1r[k],   v0[k],   r0);
            r1 = fmaf(wi1r[k+1], v0[k+1], r1);
            r2 = fmaf(w1r[k],    v1[k],   r2);
            r3 = fmaf(w1r[k+1],  v1[k+1], r3);
        }
        // h0[t]: w0.v0
        float a0 = xv, a1 = 0.f, a2 = 0.f, a3 = 0.f;
        a0 = fmaf(w0r[0], v0[0], a0);
        a1 = fmaf(w0r[1], v0[1], a1);
        a2 = fmaf(w0r[2], v0[2], a2);
        a3 = fmaf(w0r[3], v0[3], a3);
        a0 = fmaf(w0r[4], v0[4], a0);
        a1 = fmaf(w0r[5], v0[5], a1);
        a2 = fmaf(w0r[6], v0[6], a2);
        a3 = fmaf(w0r[7], v0[7], a3);
        a0 = fmaf(w0r[8], v0[8], a0);
        a1 = fmaf(w0r[9], v0[9], a1);
        h0n = fmaxf((a0 + a1) + (a2 + a3), 0.f);
        h1n = fmaxf((r0 + r1) + (r2 + r3), 0.f);
        float* sp = o2 + (size_t)(t - 1) * Hh + lane;
        if (lane < Hh) *sp = h1n;
        #pragma unroll
        for (int k = 0; k < Hh; k++) {
            v0[k] = __shfl_sync(FULL, h0n, k);
            v1[k] = __shfl_sync(FULL, h1n, k);
        }
    };

    // rest of first chunk: t = 1..3
    step(xa[1], 1);
    step(xa[2], 2);
    step(xa[3], 3);

    for (int tb = 4; tb < Tt; tb += 4) {
        #pragma unroll
        for (int d = 0; d < 4; d++) xb[d] = xp[(tb + d) * Hh + j];
        step(xb[0], tb + 0);
        step(xb[1], tb + 1);
        step(xb[2], tb + 2);
        step(xb[3], tb + 3);
    }

    // epilogue: h1[T-1] from v0 = h0[T-1], v1 = h1[T-2]
    float r0 = bias1, r1 = 0.f, r2 = 0.f, r3 = 0.f;
    #pragma unroll
    for (int k = 0; k < Hh; k += 2) {
        r0 = fmaf(wi1r[k],   v0[k],   r0);
        r1 = fmaf(wi1r[k+1], v0[k+1], r1);
        r2 = fmaf(w1r[k],    v1[k],   r2);
        r3 = fmaf(w1r[k+1],  v1[k+1], r3);
    }
    float h1f = fmaxf((r0 + r1) + (r2 + r3), 0.f);
    if (lane < Hh) o2[(size_t)(Tt - 1) * Hh + lane] = h1f;

    float* hid = dout + (size_t)BT * OUTD;       // hidden: [2][B][H]
    if (lane < Hh) {
        hid[warp * Hh + lane] = h0n;             // h0[T-1]
        hid[Bb * Hh + warp * Hh + lane] = h1f;   // h1[T-1]
    }
}

// ---------------------------------------------------------------------------
// Kernel 3: logits = out2 @ W_lin^T + b_lin, softmax over 128.
// One warp per row; lane handles outputs 4l..4l+3; coalesced STG.128.
// ---------------------------------------------------------------------------
__global__ __launch_bounds__(256) void k3_head(
    const float* __restrict__ W_lin,
    const float* __restrict__ b_lin,
    float* __restrict__ out)
{
    const unsigned FULL = 0xffffffffu;
    __shared__ float Wl[OUTD * Hh];
    __shared__ float bl[OUTD];
    int tid = threadIdx.x;
    for (int i = tid; i < OUTD * Hh; i += blockDim.x) Wl[i] = W_lin[i];
    for (int i = tid; i < OUTD; i += blockDim.x) bl[i] = b_lin[i];
    __syncthreads();

    int lane = tid & 31;
    int wib  = tid >> 5;
    float wl[4][Hh], bb[4];
    #pragma unroll
    for (int c = 0; c < 4; c++) {
        int o = 4 * lane + c;
        bb[c] = bl[o];
        #pragma unroll
        for (int k = 0; k < Hh; k++) wl[c][k] = Wl[o * Hh + k];
    }

    int wpb = blockDim.x >> 5;
    int gw  = blockIdx.x * wpb + wib;
    int nw  = gridDim.x * wpb;
    for (int row = gw; row < BT; row += nw) {
        float v = g_out2[(size_t)row * Hh + (lane < Hh ? lane : 0)];
        float hk[Hh];
        #pragma unroll
        for (int k = 0; k < Hh; k++) hk[k] = __shfl_sync(FULL, v, k);

        float acc[4];
        #pragma unroll
        for (int c = 0; c < 4; c++) {
            acc[c] = bb[c];
            #pragma unroll
            for (int k = 0; k < Hh; k++) acc[c] = fmaf(hk[k], wl[c][k], acc[c]);
        }
        float m = fmaxf(fmaxf(acc[0], acc[1]), fmaxf(acc[2], acc[3]));
        #pragma unroll
        for (int s = 16; s > 0; s >>= 1)
            m = fmaxf(m, __shfl_xor_sync(FULL, m, s));
        float e0 = __expf(acc[0] - m), e1 = __expf(acc[1] - m);
        float e2 = __expf(acc[2] - m), e3 = __expf(acc[3] - m);
        float s = e0 + e1 + e2 + e3;
        #pragma unroll
        for (int sh = 16; sh > 0; sh >>= 1)
            s += __shfl_xor_sync(FULL, s, sh);
        float r = __frcp_rn(s);
        float4 res = make_float4(e0 * r, e1 * r, e2 * r, e3 * r);
        ((float4*)(out + (size_t)row * OUTD))[lane] = res;
    }
}

// ---------------------------------------------------------------------------
extern "C" void kernel_launch(void* const* d_in, const int* in_sizes, int n_in,
                              void* d_out, int out_size)
{
    const float* x      = (const float*)d_in[0];
    const float* W_ih0  = (const float*)d_in[1];
    const float* W_hh0  = (const float*)d_in[2];
    const float* b_ih0  = (const float*)d_in[3];
    const float* b_hh0  = (const float*)d_in[4];
    const float* W_ih1  = (const float*)d_in[5];
    const float* W_hh1  = (const float*)d_in[6];
    const float* b_ih1  = (const float*)d_in[7];
    const float* b_hh1  = (const float*)d_in[8];
    const float* W_lin  = (const float*)d_in[9];
    const float* b_lin  = (const float*)d_in[10];
    float* out = (float*)d_out;

    k1_inproj<<<2048, 128>>>(x, W_ih0, b_ih0, b_hh0);             // 128-row tiles
    k2_scan<<<64, 128>>>(W_hh0, W_ih1, W_hh1, b_ih1, b_hh1, out); // 1 batch/warp
    k3_head<<<2048, 256>>>(W_lin, b_lin, out);                    // grid-stride rows
}

// round 5
// speedup vs baseline: 1.9983x; 1.3925x over previous
#include <cuda_runtime.h>
#include <cuda_bf16.h>

#define Bb 256
#define Tt 1024
#define INF 128
#define Hh 10
#define OUTD 128
#define BT (Bb*Tt)

// Scratch (no cudaMalloc allowed): device globals
__device__ float g_xp0[(size_t)BT * Hh];   // [BT][10]
__device__ float g_out2[(size_t)BT * Hh];  // [BT][10]

// ---------------------------------------------------------------------------
// Kernel 1: xp0[row][h] = dot(x[row,:], W_ih0[h,:]) + b_ih0[h] + b_hh0[h]
// (unchanged from R4: 128-row coalesced smem-staged tiles, 58.7us known)
// ---------------------------------------------------------------------------
__global__ __launch_bounds__(128) void k1_inproj(
    const float* __restrict__ x,
    const float* __restrict__ W_ih0,
    const float* __restrict__ b_ih0,
    const float* __restrict__ b_hh0)
{
    __shared__ float xs[128 * 129];
    __shared__ float4 Wq[128][3];            // Wq[f][g] = W_ih0[4g..4g+3][f]
    __shared__ float bs[16];
    int tid = threadIdx.x;
    for (int i = tid; i < 128 * 3; i += 128) {
        int f = i / 3, g = i % 3;
        float4 v;
        v.x = (4*g+0 < Hh) ? W_ih0[(4*g+0)*128 + f] : 0.f;
        v.y = (4*g+1 < Hh) ? W_ih0[(4*g+1)*128 + f] : 0.f;
        v.z = (4*g+2 < Hh) ? W_ih0[(4*g+2)*128 + f] : 0.f;
        v.w = (4*g+3 < Hh) ? W_ih0[(4*g+3)*128 + f] : 0.f;
        Wq[f][g] = v;
    }
    if (tid < Hh) bs[tid] = b_ih0[tid] + b_hh0[tid];

    const float* xrow = x + (size_t)blockIdx.x * 128 * 128;
    #pragma unroll 16
    for (int i = tid; i < 128 * 128; i += 128) {
        xs[(i >> 7) * 129 + (i & 127)] = xrow[i];
    }
    __syncthreads();

    float acc[Hh];
    #pragma unroll
    for (int h = 0; h < Hh; h++) acc[h] = bs[h];

    const float* xr = xs + tid * 129;
    #pragma unroll 8
    for (int f = 0; f < 128; f++) {
        float xv = xr[f];
        float4 wa = Wq[f][0], wb = Wq[f][1], wc = Wq[f][2];
        acc[0] = fmaf(xv, wa.x, acc[0]);
        acc[1] = fmaf(xv, wa.y, acc[1]);
        acc[2] = fmaf(xv, wa.z, acc[2]);
        acc[3] = fmaf(xv, wa.w, acc[3]);
        acc[4] = fmaf(xv, wb.x, acc[4]);
        acc[5] = fmaf(xv, wb.y, acc[5]);
        acc[6] = fmaf(xv, wb.z, acc[6]);
        acc[7] = fmaf(xv, wb.w, acc[7]);
        acc[8] = fmaf(xv, wc.x, acc[8]);
        acc[9] = fmaf(xv, wc.y, acc[9]);
    }
    float* o = g_xp0 + ((size_t)blockIdx.x * 128 + tid) * Hh;
    #pragma unroll
    for (int h = 0; h < Hh; h++) o[h] = acc[h];
}

// ---------------------------------------------------------------------------
// Kernel 2: warp-specialized 2-layer ReLU RNN scan. One block = one batch,
// 64 threads: warp0 = layer-0 producer (streams h0[t] into smem buffer),
// warp1 = layer-1 consumer (reads h0[t] via broadcast LDS.128, runs its own
// recurrence). Progress counter published every 8 steps (fence+volatile).
// Both warps run concurrently -> per-step wall = max(~55, ~50) cycles.
// ---------------------------------------------------------------------------
__global__ __launch_bounds__(64) void k2_scan(
    const float* __restrict__ W_hh0,
    const float* __restrict__ W_ih1,
    const float* __restrict__ W_hh1,
    const float* __restrict__ b_ih1,
    const float* __restrict__ b_hh1,
    float* __restrict__ dout)
{
    extern __shared__ float buf[];          // [1024][12], rows 48B (16B aligned)
    __shared__ int prog_s[8];
    const unsigned FULL = 0xffffffffu;
    int tid  = threadIdx.x;
    int wip  = tid >> 5;                    // 0 = producer, 1 = consumer
    int lane = tid & 31;
    int j    = lane < Hh ? lane : Hh - 1;
    int batch = blockIdx.x;
    volatile int* pprog = &prog_s[0];

    if (tid == 0) prog_s[0] = 0;
    __syncthreads();

    float* hid = dout + (size_t)BT * OUTD;  // hidden: [2][B][H]

    if (wip == 0) {
        // ---------------- producer: layer 0 ----------------
        float w0r[Hh];
        #pragma unroll
        for (int k = 0; k < Hh; k++) w0r[k] = W_hh0[j * Hh + k];

        const float* xp = g_xp0 + (size_t)batch * Tt * Hh;
        float v0[Hh];
        #pragma unroll
        for (int k = 0; k < Hh; k++) v0[k] = 0.f;

        float xa[8], xb[8];
        #pragma unroll
        for (int d = 0; d < 8; d++) xa[d] = xp[d * Hh + j];

        float h0n = 0.f;
        for (int tb = 0; tb < Tt; tb += 8) {
            if (tb + 8 < Tt) {
                #pragma unroll
                for (int d = 0; d < 8; d++) xb[d] = xp[(tb + 8 + d) * Hh + j];
            }
            #pragma unroll
            for (int d = 0; d < 8; d++) {
                int t = tb + d;
                float a0 = xa[d], a1 = 0.f, a2 = 0.f, a3 = 0.f;
                a0 = fmaf(w0r[0], v0[0], a0);
                a1 = fmaf(w0r[1], v0[1], a1);
                a2 = fmaf(w0r[2], v0[2], a2);
                a3 = fmaf(w0r[3], v0[3], a3);
                a0 = fmaf(w0r[4], v0[4], a0);
                a1 = fmaf(w0r[5], v0[5], a1);
                a2 = fmaf(w0r[6], v0[6], a2);
                a3 = fmaf(w0r[7], v0[7], a3);
                a0 = fmaf(w0r[8], v0[8], a0);
                a1 = fmaf(w0r[9], v0[9], a1);
                h0n = fmaxf((a0 + a1) + (a2 + a3), 0.f);
                if (lane < Hh) buf[t * 12 + lane] = h0n;
                #pragma unroll
                for (int k = 0; k < Hh; k++) v0[k] = __shfl_sync(FULL, h0n, k);
                if (d == 7) {
                    __threadfence_block();
                    if (lane == 0) *pprog = t + 1;
                }
            }
            #pragma unroll
            for (int d = 0; d < 8; d++) xa[d] = xb[d];
        }
        if (lane < Hh) hid[batch * Hh + lane] = h0n;      // h0[T-1]
    } else {
        // ---------------- consumer: layer 1 ----------------
        float wi1r[Hh], w1r[Hh];
        #pragma unroll
        for (int k = 0; k < Hh; k++) {
            wi1r[k] = W_ih1[j * Hh + k];
            w1r[k]  = W_hh1[j * Hh + k];
        }
        float bias1 = b_ih1[j] + b_hh1[j];
        float* o2 = g_out2 + (size_t)batch * Tt * Hh;

        int seen = 0;
        // wait for t=0
        if (seen < 1) { while ((seen = *pprog) < 1) { } __threadfence_block(); }
        const float4* rb0 = (const float4*)(buf);
        float4 c0 = rb0[0], c1 = rb0[1], c2 = rb0[2];

        float v1[Hh];
        #pragma unroll
        for (int k = 0; k < Hh; k++) v1[k] = 0.f;
        float h1n = 0.f;

        #pragma unroll 4
        for (int t = 0; t < Tt; t++) {
            float4 n0, n1, n2;
            if (t < Tt - 1) {
                int need = t + 2;
                if (seen < need) {
                    while ((seen = *pprog) < need) { }
                    __threadfence_block();
                }
                const float4* rb = (const float4*)(buf + (t + 1) * 12);
                n0 = rb[0]; n1 = rb[1]; n2 = rb[2];
            }
            float r0 = bias1, r1 = 0.f, r2 = 0.f, r3 = 0.f;
            r0 = fmaf(wi1r[0], c0.x, r0);
            r1 = fmaf(wi1r[1], c0.y, r1);
            r2 = fmaf(wi1r[2], c0.z, r2);
            r3 = fmaf(wi1r[3], c0.w, r3);
            r0 = fmaf(wi1r[4], c1.x, r0);
            r1 = fmaf(wi1r[5], c1.y, r1);
            r2 = fmaf(wi1r[6], c1.z, r2);
            r3 = fmaf(wi1r[7], c1.w, r3);
            r0 = fmaf(wi1r[8], c2.x, r0);
            r1 = fmaf(wi1r[9], c2.y, r1);
            r0 = fmaf(w1r[0], v1[0], r0);
            r1 = fmaf(w1r[1], v1[1], r1);
            r2 = fmaf(w1r[2], v1[2], r2);
            r3 = fmaf(w1r[3], v1[3], r3);
            r0 = fmaf(w1r[4], v1[4], r0);
            r1 = fmaf(w1r[5], v1[5], r1);
            r2 = fmaf(w1r[6], v1[6], r2);
            r3 = fmaf(w1r[7], v1[7], r3);
            r0 = fmaf(w1r[8], v1[8], r0);
            r1 = fmaf(w1r[9], v1[9], r1);
            h1n = fmaxf((r0 + r1) + (r2 + r3), 0.f);
            if (lane < Hh) o2[(size_t)t * Hh + lane] = h1n;
            #pragma unroll
            for (int k = 0; k < Hh; k++) v1[k] = __shfl_sync(FULL, h1n, k);
            c0 = n0; c1 = n1; c2 = n2;
        }
        if (lane < Hh) hid[Bb * Hh + batch * Hh + lane] = h1n;   // h1[T-1]
    }
}

// ---------------------------------------------------------------------------
// Kernel 3: logits = out2 @ W_lin^T + b_lin, softmax over 128.
// One warp per row; lane handles outputs 4l..4l+3; coalesced STG.128.
// ---------------------------------------------------------------------------
__global__ __launch_bounds__(256) void k3_head(
    const float* __restrict__ W_lin,
    const float* __restrict__ b_lin,
    float* __restrict__ out)
{
    const unsigned FULL = 0xffffffffu;
    __shared__ float Wl[OUTD * Hh];
    __shared__ float bl[OUTD];
    int tid = threadIdx.x;
    for (int i = tid; i < OUTD * Hh; i += blockDim.x) Wl[i] = W_lin[i];
    for (int i = tid; i < OUTD; i += blockDim.x) bl[i] = b_lin[i];
    __syncthreads();

    int lane = tid & 31;
    int wib  = tid >> 5;
    float wl[4][Hh], bb[4];
    #pragma unroll
    for (int c = 0; c < 4; c++) {
        int o = 4 * lane + c;
        bb[c] = bl[o];
        #pragma unroll
        for (int k = 0; k < Hh; k++) wl[c][k] = Wl[o * Hh + k];
    }

    int wpb = blockDim.x >> 5;
    int gw  = blockIdx.x * wpb + wib;
    int nw  = gridDim.x * wpb;
    for (int row = gw; row < BT; row += nw) {
        float v = g_out2[(size_t)row * Hh + (lane < Hh ? lane : 0)];
        float hk[Hh];
        #pragma unroll
        for (int k = 0; k < Hh; k++) hk[k] = __shfl_sync(FULL, v, k);

        float acc[4];
        #pragma unroll
        for (int c = 0; c < 4; c++) {
            acc[c] = bb[c];
            #pragma unroll
            for (int k = 0; k < Hh; k++) acc[c] = fmaf(hk[k], wl[c][k], acc[c]);
        }
        float m = fmaxf(fmaxf(acc[0], acc[1]), fmaxf(acc[2], acc[3]));
        #pragma unroll
        for (int s = 16; s > 0; s >>= 1)
            m = fmaxf(m, __shfl_xor_sync(FULL, m, s));
        float e0 = __expf(acc[0] - m), e1 = __expf(acc[1] - m);
        float e2 = __expf(acc[2] - m), e3 = __expf(acc[3] - m);
        float s = e0 + e1 + e2 + e3;
        #pragma unroll
        for (int sh = 16; sh > 0; sh >>= 1)
            s += __shfl_xor_sync(FULL, s, sh);
        float r = __frcp_rn(s);
        float4 res = make_float4(e0 * r, e1 * r, e2 * r, e3 * r);
        ((float4*)(out + (size_t)row * OUTD))[lane] = res;
    }
}

// ---------------------------------------------------------------------------
extern "C" void kernel_launch(void* const* d_in, const int* in_sizes, int n_in,
                              void* d_out, int out_size)
{
    const float* x      = (const float*)d_in[0];
    const float* W_ih0  = (const float*)d_in[1];
    const float* W_hh0  = (const float*)d_in[2];
    const float* b_ih0  = (const float*)d_in[3];
    const float* b_hh0  = (const float*)d_in[4];
    const float* W_ih1  = (const float*)d_in[5];
    const float* W_hh1  = (const float*)d_in[6];
    const float* b_ih1  = (const float*)d_in[7];
    const float* b_hh1  = (const float*)d_in[8];
    const float* W_lin  = (const float*)d_in[9];
    const float* b_lin  = (const float*)d_in[10];
    float* out = (float*)d_out;

    const int k2_smem = Tt * 12 * sizeof(float);   // 48KB
    cudaFuncSetAttribute(k2_scan, cudaFuncAttributeMaxDynamicSharedMemorySize,
                         k2_smem);

    k1_inproj<<<2048, 128>>>(x, W_ih0, b_ih0, b_hh0);
    k2_scan<<<Bb, 64, k2_smem>>>(W_hh0, W_ih1, W_hh1, b_ih1, b_hh1, out);
    k3_head<<<2048, 256>>>(W_lin, b_lin, out);
}

// round 6
// speedup vs baseline: 2.1039x; 1.0528x over previous
#include <cuda_runtime.h>
#include <cuda_bf16.h>

#define Bb 256
#define Tt 1024
#define INF 128
#define Hh 10
#define OUTD 128
#define BT (Bb*Tt)

// Scratch (no cudaMalloc allowed): device globals
__device__ float g_xp0[(size_t)BT * Hh];   // [BT][10]
__device__ float g_out2[(size_t)BT * Hh];  // [BT][10]

// ---------------------------------------------------------------------------
// Kernel 1: xp0[row][h] = dot(x[row,:], W_ih0[h,:]) + b_ih0[h] + b_hh0[h]
// Coalesced smem-staged x tiles (as R4/R5) + NEW: packed coalesced output.
// Old epilogue: 10 scalar STGs x 40B stride = ~10 lines/warp-STG (~400
// wavefronts/block). New: stage acc in smem (reusing xs), write the block's
// contiguous 5120B xp0 slab as STG.128 (40 lines/block = minimum).
// ---------------------------------------------------------------------------
__global__ __launch_bounds__(128) void k1_inproj(
    const float* __restrict__ x,
    const float* __restrict__ W_ih0,
    const float* __restrict__ b_ih0,
    const float* __restrict__ b_hh0)
{
    __shared__ float xs[128 * 129];
    __shared__ float4 Wq[128][3];            // Wq[f][g] = W_ih0[4g..4g+3][f]
    __shared__ float bs[16];
    int tid = threadIdx.x;
    for (int i = tid; i < 128 * 3; i += 128) {
        int f = i / 3, g = i % 3;
        float4 v;
        v.x = (4*g+0 < Hh) ? W_ih0[(4*g+0)*128 + f] : 0.f;
        v.y = (4*g+1 < Hh) ? W_ih0[(4*g+1)*128 + f] : 0.f;
        v.z = (4*g+2 < Hh) ? W_ih0[(4*g+2)*128 + f] : 0.f;
        v.w = (4*g+3 < Hh) ? W_ih0[(4*g+3)*128 + f] : 0.f;
        Wq[f][g] = v;
    }
    if (tid < Hh) bs[tid] = b_ih0[tid] + b_hh0[tid];

    const float* xrow = x + (size_t)blockIdx.x * 128 * 128;
    #pragma unroll 16
    for (int i = tid; i < 128 * 128; i += 128) {
        xs[(i >> 7) * 129 + (i & 127)] = xrow[i];
    }
    __syncthreads();

    float acc[Hh];
    #pragma unroll
    for (int h = 0; h < Hh; h++) acc[h] = bs[h];

    const float* xr = xs + tid * 129;
    #pragma unroll 8
    for (int f = 0; f < 128; f++) {
        float xv = xr[f];
        float4 wa = Wq[f][0], wb = Wq[f][1], wc = Wq[f][2];
        acc[0] = fmaf(xv, wa.x, acc[0]);
        acc[1] = fmaf(xv, wa.y, acc[1]);
        acc[2] = fmaf(xv, wa.z, acc[2]);
        acc[3] = fmaf(xv, wa.w, acc[3]);
        acc[4] = fmaf(xv, wb.x, acc[4]);
        acc[5] = fmaf(xv, wb.y, acc[5]);
        acc[6] = fmaf(xv, wb.z, acc[6]);
        acc[7] = fmaf(xv, wb.w, acc[7]);
        acc[8] = fmaf(xv, wc.x, acc[8]);
        acc[9] = fmaf(xv, wc.y, acc[9]);
    }

    // Stage results into smem (reuse xs; all xs reads are complete per-thread,
    // but other threads may lag -> sync first), then packed coalesced write.
    __syncthreads();
    float* os = xs;                          // [128][12]
    #pragma unroll
    for (int h = 0; h < Hh; h++) os[tid * 12 + h] = acc[h];
    __syncthreads();

    float4* g4 = (float4*)(g_xp0 + (size_t)blockIdx.x * 128 * Hh); // 1280 floats
    for (int i = tid; i < 320; i += 128) {   // 320 float4 = 5120B slab
        int e = i * 4;
        float4 v;
        v.x = os[(e    ) / 10 * 12 + (e    ) % 10];
        v.y = os[(e + 1) / 10 * 12 + (e + 1) % 10];
        v.z = os[(e + 2) / 10 * 12 + (e + 2) % 10];
        v.w = os[(e + 3) / 10 * 12 + (e + 3) % 10];
        g4[i] = v;
    }
}

// ---------------------------------------------------------------------------
// Kernel 2: warp-specialized 2-layer ReLU RNN scan, GROUP-GRANULAR sync.
// warp0 = layer-0 producer: branch-free 8-step groups, one unconditional
// publish per group. warp1 = layer-1 consumer: ONE poll per 8-step group
// (pprog >= tb+8 covers the whole group), branch-free inner steps with
// compile-time prefetch. Removes per-step BSSY/poll overhead (~50-100 cyc).
// ---------------------------------------------------------------------------
__global__ __launch_bounds__(64) void k2_scan(
    const float* __restrict__ W_hh0,
    const float* __restrict__ W_ih1,
    const float* __restrict__ W_hh1,
    const float* __restrict__ b_ih1,
    const float* __restrict__ b_hh1,
    float* __restrict__ dout)
{
    extern __shared__ float buf[];          // [1024][12]
    __shared__ int prog_s[8];
    const unsigned FULL = 0xffffffffu;
    int tid  = threadIdx.x;
    int wip  = tid >> 5;                    // 0 = producer, 1 = consumer
    int lane = tid & 31;
    int j    = lane < Hh ? lane : Hh - 1;
    int batch = blockIdx.x;
    volatile int* pprog = &prog_s[0];

    if (tid == 0) prog_s[0] = 0;
    __syncthreads();

    float* hid = dout + (size_t)BT * OUTD;  // hidden: [2][B][H]

    if (wip == 0) {
        // ---------------- producer: layer 0 ----------------
        float w0r[Hh];
        #pragma unroll
        for (int k = 0; k < Hh; k++) w0r[k] = W_hh0[j * Hh + k];

        const float* xp = g_xp0 + (size_t)batch * Tt * Hh;
        float v0[Hh];
        #pragma unroll
        for (int k = 0; k < Hh; k++) v0[k] = 0.f;

        float xa[8], xb[8];
        #pragma unroll
        for (int d = 0; d < 8; d++) xa[d] = xp[d * Hh + j];

        float h0n = 0.f;
        for (int tb = 0; tb < Tt; tb += 8) {
            if (tb + 8 < Tt) {
                #pragma unroll
                for (int d = 0; d < 8; d++) xb[d] = xp[(tb + 8 + d) * Hh + j];
            }
            #pragma unroll
            for (int d = 0; d < 8; d++) {
                float a0 = xa[d], a1 = 0.f, a2 = 0.f, a3 = 0.f;
                a0 = fmaf(w0r[0], v0[0], a0);
                a1 = fmaf(w0r[1], v0[1], a1);
                a2 = fmaf(w0r[2], v0[2], a2);
                a3 = fmaf(w0r[3], v0[3], a3);
                a0 = fmaf(w0r[4], v0[4], a0);
                a1 = fmaf(w0r[5], v0[5], a1);
                a2 = fmaf(w0r[6], v0[6], a2);
                a3 = fmaf(w0r[7], v0[7], a3);
                a0 = fmaf(w0r[8], v0[8], a0);
                a1 = fmaf(w0r[9], v0[9], a1);
                h0n = fmaxf((a0 + a1) + (a2 + a3), 0.f);
                if (lane < Hh) buf[(tb + d) * 12 + lane] = h0n;
                #pragma unroll
                for (int k = 0; k < Hh; k++) v0[k] = __shfl_sync(FULL, h0n, k);
            }
            __threadfence_block();
            if (lane == 0) *pprog = tb + 8;          // unconditional publish
            #pragma unroll
            for (int d = 0; d < 8; d++) xa[d] = xb[d];
        }
        if (lane < Hh) hid[batch * Hh + lane] = h0n;      // h0[T-1]
    } else {
        // ---------------- consumer: layer 1 ----------------
        float wi1r[Hh], w1r[Hh];
        #pragma unroll
        for (int k = 0; k < Hh; k++) {
            wi1r[k] = W_ih1[j * Hh + k];
            w1r[k]  = W_hh1[j * Hh + k];
        }
        float bias1 = b_ih1[j] + b_hh1[j];
        float* o2 = g_out2 + (size_t)batch * Tt * Hh;

        float v1[Hh];
        #pragma unroll
        for (int k = 0; k < Hh; k++) v1[k] = 0.f;
        float h1n = 0.f;

        int seen = 0;
        while ((seen = *pprog) < 8) { }     // wait for first group
        __threadfence_block();
        const float4* rb = (const float4*)buf;
        float4 c0 = rb[0], c1 = rb[1], c2 = rb[2];

        for (int tb = 0; tb < Tt; tb += 8) {
            #pragma unroll
            for (int d = 0; d < 8; d++) {
                float4 n0, n1, n2;
                if (d < 7) {                 // compile-time: no runtime branch
                    const float4* rn = (const float4*)(buf + (tb + d + 1) * 12);
                    n0 = rn[0]; n1 = rn[1]; n2 = rn[2];
                }
                float r0 = bias1, r1 = 0.f, r2 = 0.f, r3 = 0.f;
                r0 = fmaf(wi1r[0], c0.x, r0);
                r1 = fmaf(wi1r[1], c0.y, r1);
                r2 = fmaf(wi1r[2], c0.z, r2);
                r3 = fmaf(wi1r[3], c0.w, r3);
                r0 = fmaf(wi1r[4], c1.x, r0);
                r1 = fmaf(wi1r[5], c1.y, r1);
                r2 = fmaf(wi1r[6], c1.z, r2);
                r3 = fmaf(wi1r[7], c1.w, r3);
                r0 = fmaf(wi1r[8], c2.x, r0);
                r1 = fmaf(wi1r[9], c2.y, r1);
                r0 = fmaf(w1r[0], v1[0], r0);
                r1 = fmaf(w1r[1], v1[1], r1);
                r2 = fmaf(w1r[2], v1[2], r2);
                r3 = fmaf(w1r[3], v1[3], r3);
                r0 = fmaf(w1r[4], v1[4], r0);
                r1 = fmaf(w1r[5], v1[5], r1);
                r2 = fmaf(w1r[6], v1[6], r2);
                r3 = fmaf(w1r[7], v1[7], r3);
                r0 = fmaf(w1r[8], v1[8], r0);
                r1 = fmaf(w1r[9], v1[9], r1);
                h1n = fmaxf((r0 + r1) + (r2 + r3), 0.f);
                if (lane < Hh) o2[(size_t)(tb + d) * Hh + lane] = h1n;
                #pragma unroll
                for (int k = 0; k < Hh; k++) v1[k] = __shfl_sync(FULL, h1n, k);
                if (d < 7) { c0 = n0; c1 = n1; c2 = n2; }
            }
            if (tb + 8 < Tt) {               // one poll per group
                int need = tb + 16;
                if (seen < need) {
                    while ((seen = *pprog) < need) { }
                    __threadfence_block();
                }
                const float4* rn = (const float4*)(buf + (tb + 8) * 12);
                c0 = rn[0]; c1 = rn[1]; c2 = rn[2];
            }
        }
        if (lane < Hh) hid[Bb * Hh + batch * Hh + lane] = h1n;   // h1[T-1]
    }
}

// ---------------------------------------------------------------------------
// Kernel 3: logits = out2 @ W_lin^T + b_lin, softmax over 128.
// One warp per row; lane handles outputs 4l..4l+3; coalesced STG.128.
// ---------------------------------------------------------------------------
__global__ __launch_bounds__(256) void k3_head(
    const float* __restrict__ W_lin,
    const float* __restrict__ b_lin,
    float* __restrict__ out)
{
    const unsigned FULL = 0xffffffffu;
    __shared__ float Wl[OUTD * Hh];
    __shared__ float bl[OUTD];
    int tid = threadIdx.x;
    for (int i = tid; i < OUTD * Hh; i += blockDim.x) Wl[i] = W_lin[i];
    for (int i = tid; i < OUTD; i += blockDim.x) bl[i] = b_lin[i];
    __syncthreads();

    int lane = tid & 31;
    int wib  = tid >> 5;
    float wl[4][Hh], bb[4];
    #pragma unroll
    for (int c = 0; c < 4; c++) {
        int o = 4 * lane + c;
        bb[c] = bl[o];
        #pragma unroll
        for (int k = 0; k < Hh; k++) wl[c][k] = Wl[o * Hh + k];
    }

    int wpb = blockDim.x >> 5;
    int gw  = blockIdx.x * wpb + wib;
    int nw  = gridDim.x * wpb;
    for (int row = gw; row < BT; row += nw) {
        float v = g_out2[(size_t)row * Hh + (lane < Hh ? lane : 0)];
        float hk[Hh];
        #pragma unroll
        for (int k = 0; k < Hh; k++) hk[k] = __shfl_sync(FULL, v, k);

        float acc[4];
        #pragma unroll
        for (int c = 0; c < 4; c++) {
            acc[c] = bb[c];
            #pragma unroll
            for (int k = 0; k < Hh; k++) acc[c] = fmaf(hk[k], wl[c][k], acc[c]);
        }
        float m = fmaxf(fmaxf(acc[0], acc[1]), fmaxf(acc[2], acc[3]));
        #pragma unroll
        for (int s = 16; s > 0; s >>= 1)
            m = fmaxf(m, __shfl_xor_sync(FULL, m, s));
        float e0 = __expf(acc[0] - m), e1 = __expf(acc[1] - m);
        float e2 = __expf(acc[2] - m), e3 = __expf(acc[3] - m);
        float s = e0 + e1 + e2 + e3;
        #pragma unroll
        for (int sh = 16; sh > 0; sh >>= 1)
            s += __shfl_xor_sync(FULL, s, sh);
        float r = __frcp_rn(s);
        float4 res = make_float4(e0 * r, e1 * r, e2 * r, e3 * r);
        ((float4*)(out + (size_t)row * OUTD))[lane] = res;
    }
}

// ---------------------------------------------------------------------------
extern "C" void kernel_launch(void* const* d_in, const int* in_sizes, int n_in,
                              void* d_out, int out_size)
{
    const float* x      = (const float*)d_in[0];
    const float* W_ih0  = (const float*)d_in[1];
    const float* W_hh0  = (const float*)d_in[2];
    const float* b_ih0  = (const float*)d_in[3];
    const float* b_hh0  = (const float*)d_in[4];
    const float* W_ih1  = (const float*)d_in[5];
    const float* W_hh1  = (const float*)d_in[6];
    const float* b_ih1  = (const float*)d_in[7];
    const float* b_hh1  = (const float*)d_in[8];
    const float* W_lin  = (const float*)d_in[9];
    const float* b_lin  = (const float*)d_in[10];
    float* out = (float*)d_out;

    const int k2_smem = Tt * 12 * sizeof(float);   // 48KB
    cudaFuncSetAttribute(k2_scan, cudaFuncAttributeMaxDynamicSharedMemorySize,
                         k2_smem);

    k1_inproj<<<2048, 128>>>(x, W_ih0, b_ih0, b_hh0);
    k2_scan<<<Bb, 64, k2_smem>>>(W_hh0, W_ih1, W_hh1, b_ih1, b_hh1, out);
    k3_head<<<2048, 256>>>(W_lin, b_lin, out);
}